// round 3
// baseline (speedup 1.0000x reference)
#include <cuda_runtime.h>

// Problem dims
#define Bdim 4
#define Mdim 256
#define Ndim 128
#define Ddim 512
#define Cdim 1024
#define ROWS (Bdim*Mdim*Ndim)   // 131072

// -------- scratch (device globals; no runtime allocation) --------
__device__ float g_he[Bdim*Mdim*Ddim];    // 2 MB   he = enc @ w1[:, :D]^T
__device__ float g_hd[Bdim*Ndim*Ddim];    // 1 MB   hd = dec @ w1[:, D:]^T
__device__ float g_part[ROWS*32];         // 16 MB  per-row (max,sum) x16 chunks
__device__ float g_lse[ROWS];             // 0.5 MB

// -------- helpers --------
__device__ __forceinline__ float tanh_fast(float x){
    float r; asm("tanh.approx.f32 %0, %1;" : "=f"(r) : "f"(x)); return r;
}
__device__ __forceinline__ float to_tf32f(float x){
    unsigned r; asm("cvt.rna.tf32.f32 %0, %1;" : "=r"(r) : "f"(x));
    return __uint_as_float(r);
}
__device__ __forceinline__ void mma_tf32(float* d, const unsigned* a, const unsigned* b){
    asm volatile(
        "mma.sync.aligned.m16n8k8.row.col.f32.tf32.tf32.f32 "
        "{%0,%1,%2,%3}, {%4,%5,%6,%7}, {%8,%9}, {%0,%1,%2,%3};\n"
        : "+f"(d[0]), "+f"(d[1]), "+f"(d[2]), "+f"(d[3])
        : "r"(a[0]), "r"(a[1]), "r"(a[2]), "r"(a[3]), "r"(b[0]), "r"(b[1]));
}

// ================= K1: fc1 small GEMMs (fp32, exact) =================
// Y[row, e] = sum_d X[row, d] * W[e*1024 + woff + d]
// CTA tile 64 rows x 64 e, k-chunk 16, 256 threads, 4x4 per thread.
__global__ __launch_bounds__(256) void fc1_k(const float* __restrict__ X,
                                             const float* __restrict__ W,
                                             int woff, int which){
    __shared__ float sX[16][64];
    __shared__ float sW[16][64];
    float* __restrict__ Y = which ? g_hd : g_he;
    const int t  = threadIdx.x;
    const int tx = t & 15, ty = t >> 4;
    const int rb = blockIdx.y << 6, eb = blockIdx.x << 6;
    const int r  = t >> 2, kq = (t & 3) << 2;

    float acc[4][4];
#pragma unroll
    for (int i = 0; i < 4; i++)
#pragma unroll
        for (int j = 0; j < 4; j++) acc[i][j] = 0.f;

    for (int k0 = 0; k0 < Ddim; k0 += 16){
        float4 xv = *(const float4*)(X + (rb + r)*Ddim + k0 + kq);
        float4 wv = *(const float4*)(W + (eb + r)*(2*Ddim) + woff + k0 + kq);
        __syncthreads();
        sX[kq+0][r] = xv.x; sX[kq+1][r] = xv.y; sX[kq+2][r] = xv.z; sX[kq+3][r] = xv.w;
        sW[kq+0][r] = wv.x; sW[kq+1][r] = wv.y; sW[kq+2][r] = wv.z; sW[kq+3][r] = wv.w;
        __syncthreads();
#pragma unroll
        for (int k = 0; k < 16; k++){
            float4 a  = *(const float4*)&sX[k][ty << 2];
            float4 bv = *(const float4*)&sW[k][tx << 2];
            float av[4] = {a.x, a.y, a.z, a.w};
            float bb[4] = {bv.x, bv.y, bv.z, bv.w};
#pragma unroll
            for (int i = 0; i < 4; i++)
#pragma unroll
                for (int j = 0; j < 4; j++) acc[i][j] = fmaf(av[i], bb[j], acc[i][j]);
        }
    }
#pragma unroll
    for (int i = 0; i < 4; i++)
#pragma unroll
        for (int j = 0; j < 4; j++)
            Y[(rb + (ty<<2) + i)*Ddim + eb + (tx<<2) + j] = acc[i][j];
}

// ================= K2: fused tanh + TF32 GEMM + online softmax stats =================
// CTA: 256 rows (one (b, m..m+1) pair x all 128 n) x 128 cols, K=512, KC=16.
// 8 warps as 4(m) x 2(n), warp tile 64x64, mma m16n8k8 tf32.
// smem (dynamic, 64KB): sA[2][256][20], sB[2][128][20], sHB[2][512]
#define SA_OFF 0
#define SB_OFF 10240
#define SH_OFF 15360

__global__ __launch_bounds__(256,1) void joint_k(const float* __restrict__ b1,
                                                 const float* __restrict__ w2,
                                                 const float* __restrict__ b2,
                                                 float* __restrict__ out){
    extern __shared__ float smem[];
    float* sA  = smem + SA_OFF;   // [2][256][20]
    float* sB  = smem + SB_OFF;   // [2][128][20]
    float* sHB = smem + SH_OFF;   // [2][512]  he(+b1) for the two m rows

    const int bid = blockIdx.x;
    const int bm2 = bid >> 3;       // 0..511  (256-row block)
    const int ci  = bid & 7;        // 0..7    (128-col block)
    const int t   = threadIdx.x;
    const int w   = t >> 5, l = t & 31;
    const int wm  = w >> 1, wn = w & 1;
    const int lq  = l >> 2, lr = l & 3;
    const int g0  = bm2 << 8;       // first global row
    const int b   = bm2 >> 7;       // batch index

    const float* __restrict__ hdB = g_hd + (b << 16);          // b*128*512
    const float* __restrict__ w2B = w2   + ((ci << 7) << 9);   // (ci*128)*512

    // ---- load sHB = he + b1 for both m rows ----
    {
        const int j = t >> 7;           // which m row
        const int e = (t & 127) << 2;   // float4 offset
        float4 h  = *(const float4*)(g_he + (((bm2 << 1) + j) << 9) + e);
        float4 bb = *(const float4*)(b1 + e);
        float4 v; v.x = h.x + bb.x; v.y = h.y + bb.y; v.z = h.z + bb.z; v.w = h.w + bb.w;
        *(float4*)(sHB + (j << 9) + e) = v;
    }

    const int pr  = t >> 2;         // 0..63: row quarter-group
    const int kq4 = (t & 3) << 2;   // 0,4,8,12: k quad within chunk

    float4 hdR[2], wR[2];
    float acc[4][8][4];
#pragma unroll
    for (int mt = 0; mt < 4; mt++)
#pragma unroll
        for (int nt = 0; nt < 8; nt++)
#pragma unroll
            for (int i = 0; i < 4; i++) acc[mt][nt][i] = 0.f;

    // ---- gload chunk 0 ----
    {
        const int koff = 0*16 + kq4;
        hdR[0] = *(const float4*)(hdB + ( pr       << 9) + koff);
        hdR[1] = *(const float4*)(hdB + ((pr + 64) << 9) + koff);
        wR[0]  = *(const float4*)(w2B + ( pr       << 9) + koff);
        wR[1]  = *(const float4*)(w2B + ((pr + 64) << 9) + koff);
    }
    __syncthreads();   // sHB ready

    // ---- process+store chunk 0 into buf 0 ----
    {
        const int kc = 0;
        float4 h0 = *(const float4*)(sHB +        kc*16 + kq4);
        float4 h1 = *(const float4*)(sHB + 512 +  kc*16 + kq4);
#pragma unroll
        for (int j = 0; j < 2; j++){
            const int n = pr + (j << 6);
            float4 d = hdR[j], v;
            v.x = to_tf32f(tanh_fast(h0.x + d.x)); v.y = to_tf32f(tanh_fast(h0.y + d.y));
            v.z = to_tf32f(tanh_fast(h0.z + d.z)); v.w = to_tf32f(tanh_fast(h0.w + d.w));
            *(float4*)(sA + n*20 + kq4) = v;
            v.x = to_tf32f(tanh_fast(h1.x + d.x)); v.y = to_tf32f(tanh_fast(h1.y + d.y));
            v.z = to_tf32f(tanh_fast(h1.z + d.z)); v.w = to_tf32f(tanh_fast(h1.w + d.w));
            *(float4*)(sA + (128 + n)*20 + kq4) = v;
            float4 wv = wR[j], u;
            u.x = to_tf32f(wv.x); u.y = to_tf32f(wv.y); u.z = to_tf32f(wv.z); u.w = to_tf32f(wv.w);
            *(float4*)(sB + n*20 + kq4) = u;
        }
    }
    __syncthreads();

    int buf = 0;
#pragma unroll 1
    for (int kc = 0; kc < 32; kc++){
        // prefetch next chunk from global
        if (kc < 31){
            const int koff = (kc + 1)*16 + kq4;
            hdR[0] = *(const float4*)(hdB + ( pr       << 9) + koff);
            hdR[1] = *(const float4*)(hdB + ((pr + 64) << 9) + koff);
            wR[0]  = *(const float4*)(w2B + ( pr       << 9) + koff);
            wR[1]  = *(const float4*)(w2B + ((pr + 64) << 9) + koff);
        }
        // mma over current chunk
        {
            const float* A  = sA + buf*5120;
            const float* Bm = sB + buf*2560;
#pragma unroll
            for (int k8s = 0; k8s < 2; k8s++){
                const int kb = (k8s << 3) + lr;
                unsigned af[4][4], bf[8][2];
#pragma unroll
                for (int mt = 0; mt < 4; mt++){
                    const int rr = (wm << 6) + (mt << 4) + lq;
                    af[mt][0] = __float_as_uint(A[ rr     *20 + kb    ]);
                    af[mt][1] = __float_as_uint(A[(rr + 8)*20 + kb    ]);
                    af[mt][2] = __float_as_uint(A[ rr     *20 + kb + 4]);
                    af[mt][3] = __float_as_uint(A[(rr + 8)*20 + kb + 4]);
                }
#pragma unroll
                for (int nt = 0; nt < 8; nt++){
                    const int cc = (wn << 6) + (nt << 3) + lq;
                    bf[nt][0] = __float_as_uint(Bm[cc*20 + kb    ]);
                    bf[nt][1] = __float_as_uint(Bm[cc*20 + kb + 4]);
                }
#pragma unroll
                for (int mt = 0; mt < 4; mt++)
#pragma unroll
                    for (int nt = 0; nt < 8; nt++)
                        mma_tf32(acc[mt][nt], af[mt], bf[nt]);
            }
        }
        // convert+store next chunk into other buffer
        if (kc < 31){
            const int nk = kc + 1;
            float*  dA = sA + (buf ^ 1)*5120;
            float*  dB = sB + (buf ^ 1)*2560;
            float4 h0 = *(const float4*)(sHB +        nk*16 + kq4);
            float4 h1 = *(const float4*)(sHB + 512 +  nk*16 + kq4);
#pragma unroll
            for (int j = 0; j < 2; j++){
                const int n = pr + (j << 6);
                float4 d = hdR[j], v;
                v.x = to_tf32f(tanh_fast(h0.x + d.x)); v.y = to_tf32f(tanh_fast(h0.y + d.y));
                v.z = to_tf32f(tanh_fast(h0.z + d.z)); v.w = to_tf32f(tanh_fast(h0.w + d.w));
                *(float4*)(dA + n*20 + kq4) = v;
                v.x = to_tf32f(tanh_fast(h1.x + d.x)); v.y = to_tf32f(tanh_fast(h1.y + d.y));
                v.z = to_tf32f(tanh_fast(h1.z + d.z)); v.w = to_tf32f(tanh_fast(h1.w + d.w));
                *(float4*)(dA + (128 + n)*20 + kq4) = v;
                float4 wv = wR[j], u;
                u.x = to_tf32f(wv.x); u.y = to_tf32f(wv.y); u.z = to_tf32f(wv.z); u.w = to_tf32f(wv.w);
                *(float4*)(dB + n*20 + kq4) = u;
            }
        }
        __syncthreads();
        buf ^= 1;
    }

    // ---- epilogue: +b2, store logits, per-row online (max, sumexp) per 64-col chunk ----
    const int colb = (ci << 7) + (wn << 6);
#pragma unroll
    for (int mt = 0; mt < 4; mt++){
#pragma unroll
        for (int h = 0; h < 2; h++){
            const int r = (wm << 6) + (mt << 4) + lq + (h << 3);
            const int g = g0 + r;
            float v[16];
            float mx = -3.4e38f;
#pragma unroll
            for (int nt = 0; nt < 8; nt++){
                const int c = colb + (nt << 3) + (lr << 1);
                float x0 = acc[mt][nt][h*2 + 0] + __ldg(b2 + c);
                float x1 = acc[mt][nt][h*2 + 1] + __ldg(b2 + c + 1);
                v[2*nt] = x0; v[2*nt + 1] = x1;
                mx = fmaxf(mx, fmaxf(x0, x1));
                float2 st; st.x = x0; st.y = x1;
                *(float2*)(out + g*Cdim + c) = st;
            }
            mx = fmaxf(mx, __shfl_xor_sync(0xffffffffu, mx, 1));
            mx = fmaxf(mx, __shfl_xor_sync(0xffffffffu, mx, 2));
            float s = 0.f;
#pragma unroll
            for (int i = 0; i < 16; i++) s += __expf(v[i] - mx);
            s += __shfl_xor_sync(0xffffffffu, s, 1);
            s += __shfl_xor_sync(0xffffffffu, s, 2);
            if (lr == 0){
                float2 p; p.x = mx; p.y = s;
                *(float2*)(g_part + g*32 + (((ci << 1) + wn) << 1)) = p;
            }
        }
    }
}

// ================= K3: combine 16 partials/row -> lse =================
__global__ __launch_bounds__(256) void lse_k(){
    const int g = blockIdx.x*256 + threadIdx.x;
    const float* p = g_part + g*32;
    float pm[16], ps[16];
    float mx = -3.4e38f;
#pragma unroll
    for (int i = 0; i < 16; i++){ pm[i] = p[2*i]; ps[i] = p[2*i + 1]; mx = fmaxf(mx, pm[i]); }
    float s = 0.f;
#pragma unroll
    for (int i = 0; i < 16; i++) s += ps[i]*__expf(pm[i] - mx);
    g_lse[g] = mx + __logf(s);
}

// ================= K4: out[row, c] -= lse[row] (in place, float4) =================
__global__ __launch_bounds__(256) void sub_k(float* __restrict__ out){
    const int i = blockIdx.x*256 + threadIdx.x;     // float4 index
    const float l = __ldg(g_lse + (i >> 8));        // 256 float4 per row
    float4 v = ((const float4*)out)[i];
    v.x -= l; v.y -= l; v.z -= l; v.w -= l;
    ((float4*)out)[i] = v;
}

// ================= launch =================
extern "C" void kernel_launch(void* const* d_in, const int* in_sizes, int n_in,
                              void* d_out, int out_size){
    (void)in_sizes; (void)n_in; (void)out_size;
    const float* enc = (const float*)d_in[0];
    const float* dec = (const float*)d_in[1];
    const float* w1  = (const float*)d_in[2];
    const float* b1  = (const float*)d_in[3];
    const float* w2  = (const float*)d_in[4];
    const float* b2  = (const float*)d_in[5];
    float* out = (float*)d_out;

    cudaFuncSetAttribute(joint_k, cudaFuncAttributeMaxDynamicSharedMemorySize, 65536);

    fc1_k<<<dim3(8, 16), 256>>>(enc, w1, 0,    0);   // he: 1024 rows
    fc1_k<<<dim3(8, 8),  256>>>(dec, w1, Ddim, 1);   // hd: 512 rows
    joint_k<<<4096, 256, 65536>>>(b1, w2, b2, out);
    lse_k<<<ROWS/256, 256>>>();
    sub_k<<<(ROWS*Cdim/4)/256, 256>>>(out);
}

// round 5
// speedup vs baseline: 1.4484x; 1.4484x over previous
#include <cuda_runtime.h>
#include <cuda_bf16.h>
#include <cstdint>

// Problem dims
#define Bdim 4
#define Mdim 256
#define Ndim 128
#define Ddim 512
#define Cdim 1024
#define ROWS (Bdim*Mdim*Ndim)   // 131072

// -------- scratch (device globals) --------
__device__ float g_he[Bdim*Mdim*Ddim];          // 2 MB
__device__ float g_hd[Bdim*Ndim*Ddim];          // 1 MB
__device__ __nv_bfloat16 g_w2b[Cdim*Ddim];      // 1 MB  w2 rounded to bf16
__device__ float g_part[ROWS*32];               // 16 MB (max,sum) x16 per row
__device__ float g_lse[ROWS];                   // 0.5 MB

// -------- helpers --------
__device__ __forceinline__ float tanh_fast(float x){
    float r; asm("tanh.approx.f32 %0, %1;" : "=f"(r) : "f"(x)); return r;
}
// pack two floats -> bf16x2 (lo = first/lower-k element)
__device__ __forceinline__ unsigned pk(float lo, float hi){
    unsigned r;
    asm("cvt.rn.bf16x2.f32 %0, %2, %1;" : "=r"(r) : "f"(lo), "f"(hi));
    return r;
}
__device__ __forceinline__ void mma_bf16(float* d, const unsigned* a, const unsigned* b){
    asm volatile(
        "mma.sync.aligned.m16n8k16.row.col.f32.bf16.bf16.f32 "
        "{%0,%1,%2,%3}, {%4,%5,%6,%7}, {%8,%9}, {%0,%1,%2,%3};\n"
        : "+f"(d[0]), "+f"(d[1]), "+f"(d[2]), "+f"(d[3])
        : "r"(a[0]), "r"(a[1]), "r"(a[2]), "r"(a[3]), "r"(b[0]), "r"(b[1]));
}

// ================= K0: round w2 -> bf16 =================
// each thread converts 8 floats -> 8 bf16 (one uint4 store)
__global__ __launch_bounds__(256) void cvtw2b_k(const float* __restrict__ w2){
    const int i = blockIdx.x*256 + threadIdx.x;
    float4 v0 = ((const float4*)w2)[2*i];
    float4 v1 = ((const float4*)w2)[2*i + 1];
    uint4 o;
    o.x = pk(v0.x, v0.y); o.y = pk(v0.z, v0.w);
    o.z = pk(v1.x, v1.y); o.w = pk(v1.z, v1.w);
    ((uint4*)g_w2b)[i] = o;
}

// ================= K1: fc1 small GEMMs (fp32, exact) =================
__global__ __launch_bounds__(256) void fc1_k(const float* __restrict__ X,
                                             const float* __restrict__ W,
                                             int woff, int which){
    __shared__ float sX[16][64];
    __shared__ float sW[16][64];
    float* __restrict__ Y = which ? g_hd : g_he;
    const int t  = threadIdx.x;
    const int tx = t & 15, ty = t >> 4;
    const int rb = blockIdx.y << 6, eb = blockIdx.x << 6;
    const int r  = t >> 2, kq = (t & 3) << 2;

    float acc[4][4];
#pragma unroll
    for (int i = 0; i < 4; i++)
#pragma unroll
        for (int j = 0; j < 4; j++) acc[i][j] = 0.f;

    for (int k0 = 0; k0 < Ddim; k0 += 16){
        float4 xv = *(const float4*)(X + (rb + r)*Ddim + k0 + kq);
        float4 wv = *(const float4*)(W + (eb + r)*(2*Ddim) + woff + k0 + kq);
        __syncthreads();
        sX[kq+0][r] = xv.x; sX[kq+1][r] = xv.y; sX[kq+2][r] = xv.z; sX[kq+3][r] = xv.w;
        sW[kq+0][r] = wv.x; sW[kq+1][r] = wv.y; sW[kq+2][r] = wv.z; sW[kq+3][r] = wv.w;
        __syncthreads();
#pragma unroll
        for (int k = 0; k < 16; k++){
            float4 a  = *(const float4*)&sX[k][ty << 2];
            float4 bv = *(const float4*)&sW[k][tx << 2];
            float av[4] = {a.x, a.y, a.z, a.w};
            float bb[4] = {bv.x, bv.y, bv.z, bv.w};
#pragma unroll
            for (int i = 0; i < 4; i++)
#pragma unroll
                for (int j = 0; j < 4; j++) acc[i][j] = fmaf(av[i], bb[j], acc[i][j]);
        }
    }
#pragma unroll
    for (int i = 0; i < 4; i++)
#pragma unroll
        for (int j = 0; j < 4; j++)
            Y[(rb + (ty<<2) + i)*Ddim + eb + (tx<<2) + j] = acc[i][j];
}

// ================= K2: fused tanh + bf16 mma.sync GEMM + softmax stats =========
// CTA: 256 rows (2 m x 128 n) x 128 cols, K=512 in 16 chunks of 32.
// 8 warps as 4(m) x 2(n), warp tile 64x64, mma m16n8k16 bf16.
// smem layout (bytes):
//   [0, 4096)      sHB: he+b1 [2][512] float
//   [4096, 45056)  sA:  2 bufs x 256 rows x 80B (32 bf16 + pad)
//   [45056, 65536) sB:  2 bufs x 128 rows x 80B
#define SHB_OFF 0
#define SA_OFF  4096
#define SB_OFF  45056
#define A_BUF   20480
#define B_BUF   10240

__global__ __launch_bounds__(256,1) void joint_k(const float* __restrict__ b1,
                                                 const float* __restrict__ b2,
                                                 float* __restrict__ out){
    extern __shared__ __align__(128) char smemc[];
    float* sHB = (float*)(smemc + SHB_OFF);

    const int bid = blockIdx.x;
    const int bm2 = bid >> 3;       // 0..511  (256-row block = 2 m rows)
    const int ci  = bid & 7;        // 0..7    (128-col block)
    const int t   = threadIdx.x;
    const int w   = t >> 5, l = t & 31;
    const int wm  = w >> 1, wn = w & 1;
    const int lq  = l >> 2, lr = l & 3;
    const int g0  = bm2 << 8;
    const int b   = bm2 >> 7;

    const float* __restrict__ hdB = g_hd + (b << 16);
    const __nv_bfloat16* __restrict__ w2B = g_w2b + ((size_t)(ci << 7) << 9);

    // ---- load sHB = he + b1 for both m rows ----
    {
        const int j = t >> 7;
        const int e = (t & 127) << 2;
        float4 h  = *(const float4*)(g_he + (((bm2 << 1) + j) << 9) + e);
        float4 bb = *(const float4*)(b1 + e);
        float4 v; v.x = h.x + bb.x; v.y = h.y + bb.y; v.z = h.z + bb.z; v.w = h.w + bb.w;
        *(float4*)(sHB + (j << 9) + e) = v;
    }

    const int pr  = t >> 2;         // 0..63
    const int kq8 = (t & 3) << 3;   // k offset within 32-chunk (floats)
    const int sc  = (t & 3) << 4;   // byte offset of 16B slot within row

    float4 hdv[2][2];   // [n-half][k-half]
    uint4  wv[2];
    float acc[4][8][4];
#pragma unroll
    for (int mt = 0; mt < 4; mt++)
#pragma unroll
        for (int nt = 0; nt < 8; nt++)
#pragma unroll
            for (int i = 0; i < 4; i++) acc[mt][nt][i] = 0.f;

    // ---- prefetch chunk 0 ----
    {
        const float* h0 = hdB + pr*Ddim + kq8;
        const float* h1 = hdB + (pr + 64)*Ddim + kq8;
        hdv[0][0] = *(const float4*)h0; hdv[0][1] = *(const float4*)(h0 + 4);
        hdv[1][0] = *(const float4*)h1; hdv[1][1] = *(const float4*)(h1 + 4);
        wv[0] = *(const uint4*)(w2B + pr*Ddim + kq8);
        wv[1] = *(const uint4*)(w2B + (pr + 64)*Ddim + kq8);
    }
    __syncthreads();   // sHB ready

    // ---- produce chunk 0 into buf 0 ----
    {
        const float* hb = sHB + kq8;
        float4 e0a = *(const float4*)hb,        e0b = *(const float4*)(hb + 4);
        float4 e1a = *(const float4*)(hb + 512), e1b = *(const float4*)(hb + 516);
        char* dA = smemc + SA_OFF;
        char* dB = smemc + SB_OFF;
#pragma unroll
        for (int j = 0; j < 2; j++){
            float4 d0 = hdv[j][0], d1 = hdv[j][1];
            uint4 o;
            o.x = pk(tanh_fast(e0a.x + d0.x), tanh_fast(e0a.y + d0.y));
            o.y = pk(tanh_fast(e0a.z + d0.z), tanh_fast(e0a.w + d0.w));
            o.z = pk(tanh_fast(e0b.x + d1.x), tanh_fast(e0b.y + d1.y));
            o.w = pk(tanh_fast(e0b.z + d1.z), tanh_fast(e0b.w + d1.w));
            *(uint4*)(dA + (pr + (j << 6))*80 + sc) = o;
            o.x = pk(tanh_fast(e1a.x + d0.x), tanh_fast(e1a.y + d0.y));
            o.y = pk(tanh_fast(e1a.z + d0.z), tanh_fast(e1a.w + d0.w));
            o.z = pk(tanh_fast(e1b.x + d1.x), tanh_fast(e1b.y + d1.y));
            o.w = pk(tanh_fast(e1b.z + d1.z), tanh_fast(e1b.w + d1.w));
            *(uint4*)(dA + (128 + pr + (j << 6))*80 + sc) = o;
            *(uint4*)(dB + (pr + (j << 6))*80 + sc) = wv[j];
        }
    }
    __syncthreads();

    int buf = 0;
#pragma unroll 1
    for (int kc = 0; kc < 16; kc++){
        // prefetch next chunk from global
        if (kc < 15){
            const int ko = (kc + 1)*32 + kq8;
            const float* h0 = hdB + pr*Ddim + ko;
            const float* h1 = hdB + (pr + 64)*Ddim + ko;
            hdv[0][0] = *(const float4*)h0; hdv[0][1] = *(const float4*)(h0 + 4);
            hdv[1][0] = *(const float4*)h1; hdv[1][1] = *(const float4*)(h1 + 4);
            wv[0] = *(const uint4*)(w2B + pr*Ddim + ko);
            wv[1] = *(const uint4*)(w2B + (pr + 64)*Ddim + ko);
        }
        // mma over current chunk (2 k16 steps)
        {
            const char* A  = smemc + SA_OFF + buf*A_BUF;
            const char* Bm = smemc + SB_OFF + buf*B_BUF;
#pragma unroll
            for (int s = 0; s < 2; s++){
                const int off = (s << 5) + (lr << 2);
                unsigned af[4][4], bf[8][2];
#pragma unroll
                for (int mt = 0; mt < 4; mt++){
                    const char* ap = A + ((wm << 6) + (mt << 4) + lq)*80 + off;
                    af[mt][0] = *(const unsigned*)ap;
                    af[mt][1] = *(const unsigned*)(ap + 640);
                    af[mt][2] = *(const unsigned*)(ap + 16);
                    af[mt][3] = *(const unsigned*)(ap + 656);
                }
#pragma unroll
                for (int nt = 0; nt < 8; nt++){
                    const char* bp = Bm + ((wn << 6) + (nt << 3) + lq)*80 + off;
                    bf[nt][0] = *(const unsigned*)bp;
                    bf[nt][1] = *(const unsigned*)(bp + 16);
                }
#pragma unroll
                for (int mt = 0; mt < 4; mt++)
#pragma unroll
                    for (int nt = 0; nt < 8; nt++)
                        mma_bf16(acc[mt][nt], af[mt], bf[nt]);
            }
        }
        // produce next chunk into other buffer
        if (kc < 15){
            const int nk = kc + 1;
            const float* hb = sHB + nk*32 + kq8;
            float4 e0a = *(const float4*)hb,         e0b = *(const float4*)(hb + 4);
            float4 e1a = *(const float4*)(hb + 512), e1b = *(const float4*)(hb + 516);
            char* dA = smemc + SA_OFF + (buf ^ 1)*A_BUF;
            char* dB = smemc + SB_OFF + (buf ^ 1)*B_BUF;
#pragma unroll
            for (int j = 0; j < 2; j++){
                float4 d0 = hdv[j][0], d1 = hdv[j][1];
                uint4 o;
                o.x = pk(tanh_fast(e0a.x + d0.x), tanh_fast(e0a.y + d0.y));
                o.y = pk(tanh_fast(e0a.z + d0.z), tanh_fast(e0a.w + d0.w));
                o.z = pk(tanh_fast(e0b.x + d1.x), tanh_fast(e0b.y + d1.y));
                o.w = pk(tanh_fast(e0b.z + d1.z), tanh_fast(e0b.w + d1.w));
                *(uint4*)(dA + (pr + (j << 6))*80 + sc) = o;
                o.x = pk(tanh_fast(e1a.x + d0.x), tanh_fast(e1a.y + d0.y));
                o.y = pk(tanh_fast(e1a.z + d0.z), tanh_fast(e1a.w + d0.w));
                o.z = pk(tanh_fast(e1b.x + d1.x), tanh_fast(e1b.y + d1.y));
                o.w = pk(tanh_fast(e1b.z + d1.z), tanh_fast(e1b.w + d1.w));
                *(uint4*)(dA + (128 + pr + (j << 6))*80 + sc) = o;
                *(uint4*)(dB + (pr + (j << 6))*80 + sc) = wv[j];
            }
        }
        __syncthreads();
        buf ^= 1;
    }

    // ---- epilogue: +b2, store logits, per-row online (max, sumexp) partials ----
    const int colb = (ci << 7) + (wn << 6);
#pragma unroll
    for (int mt = 0; mt < 4; mt++){
#pragma unroll
        for (int h = 0; h < 2; h++){
            const int r = (wm << 6) + (mt << 4) + lq + (h << 3);
            const int g = g0 + r;
            float v[16];
            float mx = -3.4e38f;
#pragma unroll
            for (int nt = 0; nt < 8; nt++){
                const int c = colb + (nt << 3) + (lr << 1);
                float x0 = acc[mt][nt][h*2 + 0] + __ldg(b2 + c);
                float x1 = acc[mt][nt][h*2 + 1] + __ldg(b2 + c + 1);
                v[2*nt] = x0; v[2*nt + 1] = x1;
                mx = fmaxf(mx, fmaxf(x0, x1));
                float2 st; st.x = x0; st.y = x1;
                *(float2*)(out + (size_t)g*Cdim + c) = st;
            }
            mx = fmaxf(mx, __shfl_xor_sync(0xffffffffu, mx, 1));
            mx = fmaxf(mx, __shfl_xor_sync(0xffffffffu, mx, 2));
            float s = 0.f;
#pragma unroll
            for (int i = 0; i < 16; i++) s += __expf(v[i] - mx);
            s += __shfl_xor_sync(0xffffffffu, s, 1);
            s += __shfl_xor_sync(0xffffffffu, s, 2);
            if (lr == 0){
                float2 p; p.x = mx; p.y = s;
                *(float2*)(g_part + (size_t)g*32 + (((ci << 1) + wn) << 1)) = p;
            }
        }
    }
}

// ================= K3: combine 16 partials/row -> lse =================
__global__ __launch_bounds__(256) void lse_k(){
    const int g = blockIdx.x*256 + threadIdx.x;
    const float* p = g_part + (size_t)g*32;
    float pm[16], ps[16];
    float mx = -3.4e38f;
#pragma unroll
    for (int i = 0; i < 16; i++){ pm[i] = p[2*i]; ps[i] = p[2*i + 1]; mx = fmaxf(mx, pm[i]); }
    float s = 0.f;
#pragma unroll
    for (int i = 0; i < 16; i++) s += ps[i]*__expf(pm[i] - mx);
    g_lse[g] = mx + __logf(s);
}

// ================= K4: out[row, c] -= lse[row] =================
__global__ __launch_bounds__(256) void sub_k(float* __restrict__ out){
    const int i = blockIdx.x*256 + threadIdx.x;     // float4 index
    const float l = __ldg(g_lse + (i >> 8));
    float4 v = ((const float4*)out)[i];
    v.x -= l; v.y -= l; v.z -= l; v.w -= l;
    ((float4*)out)[i] = v;
}

// ================= launch =================
extern "C" void kernel_launch(void* const* d_in, const int* in_sizes, int n_in,
                              void* d_out, int out_size){
    (void)in_sizes; (void)n_in; (void)out_size;
    const float* enc = (const float*)d_in[0];
    const float* dec = (const float*)d_in[1];
    const float* w1  = (const float*)d_in[2];
    const float* b1  = (const float*)d_in[3];
    const float* w2  = (const float*)d_in[4];
    const float* b2  = (const float*)d_in[5];
    float* out = (float*)d_out;

    cudaFuncSetAttribute(joint_k, cudaFuncAttributeMaxDynamicSharedMemorySize, 65536);

    cvtw2b_k<<<(Cdim*Ddim/8)/256, 256>>>(w2);
    fc1_k<<<dim3(8, 16), 256>>>(enc, w1, 0,    0);   // he
    fc1_k<<<dim3(8, 8),  256>>>(dec, w1, Ddim, 1);   // hd
    joint_k<<<4096, 256, 65536>>>(b1, b2, out);
    lse_k<<<ROWS/256, 256>>>();
    sub_k<<<(ROWS*Cdim/4)/256, 256>>>(out);
}